// round 1
// baseline (speedup 1.0000x reference)
#include <cuda_runtime.h>
#include <math.h>
#include <stdint.h>

// Problem constants
#define NUC 80000
#define NPC 40000
#define NEC 160000
#define DMC 256
#define NHC 4
#define NDC 64

static const size_t SZ_U = (size_t)NUC * DMC;   // 20,480,000
static const size_t SZ_P = (size_t)NPC * DMC;   // 10,240,000

// Scratch layout (floats) in one big __device__ array
static const size_t OFF_XUA   = 0;
static const size_t OFF_XUB   = SZ_U;
static const size_t OFF_QU    = 2 * SZ_U;
static const size_t OFF_KTU   = 3 * SZ_U;
static const size_t OFF_VTU   = 4 * SZ_U;
static const size_t OFF_AGGU  = 5 * SZ_U;
static const size_t OFF_XPB   = 6 * SZ_U;
static const size_t OFF_QP    = OFF_XPB + SZ_P;
static const size_t OFF_KTP   = OFF_XPB + 2 * SZ_P;
static const size_t OFF_VTP   = OFF_XPB + 3 * SZ_P;
static const size_t OFF_AGGP  = OFF_XPB + 4 * SZ_P;
static const size_t OFF_LOG   = OFF_XPB + 5 * SZ_P;            // E*H = 640,000
static const size_t OFF_M     = OFF_LOG + (size_t)NEC * NHC;   // NU*H = 320,000
static const size_t OFF_S     = OFF_M + (size_t)NUC * NHC;
static const size_t OFF_WF    = OFF_S + (size_t)NUC * NHC;     // 8 * 65536
static const size_t OFF_BF    = OFF_WF + (size_t)8 * DMC * DMC; // 8 * 256
static const size_t TOTAL_F   = OFF_BF + 8 * DMC;

__device__ float g_buf[TOTAL_F];

// ---------------------------------------------------------------------------
__device__ __forceinline__ float gelu_f(float x) {
    return 0.5f * x * (1.0f + erff(x * 0.70710678118654752f));
}

__device__ __forceinline__ void atomicMaxF(float* addr, float v) {
    if (v >= 0.0f) atomicMax((int*)addr, __float_as_int(v));
    else           atomicMin((unsigned int*)addr, __float_as_uint(v));
}

// ---------------------------------------------------------------------------
// Fused relation weights: Wf[c][i][h*64+e] = sum_d Wsrc[lt][i][h*64+d] * R[lt][h][d][e]
// c = kv*4 + l*2 + t   (kv: 0 = K/arel, 1 = V/mrel)
__global__ void fuse_w_kernel(const float* __restrict__ Wk, const float* __restrict__ Wv,
                              const float* __restrict__ arel, const float* __restrict__ mrel,
                              float* __restrict__ Wf) {
    int c = blockIdx.x;        // 0..7
    int i = blockIdx.y;        // 0..255 (row)
    int j = threadIdx.x;       // 0..255 (col)
    int kv = c >> 2;
    int lt = c & 3;
    const float* Wsrc = (kv ? Wv : Wk) + (size_t)lt * DMC * DMC;
    const float* R    = (kv ? mrel : arel) + (size_t)lt * NHC * NDC * NDC;
    int h = j >> 6, e = j & 63;
    const float* wrow = Wsrc + (size_t)i * DMC + h * NDC;
    const float* rr   = R + (size_t)h * NDC * NDC + e;
    float sum = 0.0f;
#pragma unroll 8
    for (int d = 0; d < NDC; d++) sum = fmaf(wrow[d], rr[(size_t)d * NDC], sum);
    Wf[(size_t)c * DMC * DMC + (size_t)i * DMC + j] = sum;
}

__global__ void fuse_b_kernel(const float* __restrict__ bk, const float* __restrict__ bv,
                              const float* __restrict__ arel, const float* __restrict__ mrel,
                              float* __restrict__ bf) {
    int c = blockIdx.x;        // 0..7
    int j = threadIdx.x;       // 0..255
    int kv = c >> 2;
    int lt = c & 3;
    const float* bsrc = (kv ? bv : bk) + (size_t)lt * DMC;
    const float* R    = (kv ? mrel : arel) + (size_t)lt * NHC * NDC * NDC;
    int h = j >> 6, e = j & 63;
    float sum = 0.0f;
#pragma unroll 8
    for (int d = 0; d < NDC; d++)
        sum = fmaf(bsrc[h * NDC + d], R[(size_t)h * NDC * NDC + (size_t)d * NDC + e], sum);
    bf[(size_t)c * DMC + j] = sum;
}

// ---------------------------------------------------------------------------
// Gather user embeddings: out[row] = table[ids[row]]  (float4 granularity)
__global__ void gather_kernel(const int* __restrict__ ids, const float* __restrict__ tab,
                              float* __restrict__ out) {
    size_t i = (size_t)blockIdx.x * blockDim.x + threadIdx.x;  // over NU * 64
    if (i >= (size_t)NUC * (DMC / 4)) return;
    size_t row = i >> 6;
    int c4 = (int)(i & 63);
    ((float4*)out)[i] = ((const float4*)(tab + (size_t)ids[row] * DMC))[c4];
}

// ---------------------------------------------------------------------------
// SGEMM: C[M,256] = A[M,256] @ W[256,256] + bias, with optional skip+gelu epilogue
// mode 0: plain     mode 1: C = beta*(AW+b) + (1-beta)*xold, beta = sigmoid(*skipPtr)
// gelu_after: apply exact gelu to the final value
__global__ __launch_bounds__(256)
void gemm_kernel(const float* __restrict__ A, const float* __restrict__ W,
                 const float* __restrict__ bias, float* __restrict__ C,
                 int mode, const float* __restrict__ xold,
                 const float* __restrict__ skipPtr, int gelu_after) {
    __shared__ float As[16][64];
    __shared__ float Ws[16][64];
    const int bm = blockIdx.y * 64;
    const int bn = blockIdx.x * 64;
    const int t  = threadIdx.x;
    const int ty = t >> 4, tx = t & 15;
    const int la_r = t >> 2;            // A tile row this thread loads
    const int la_c = (t & 3) << 2;      // A tile col (float4)
    const int lw_k = t >> 4;            // W tile k-row
    const int lw_j = (t & 15) << 2;     // W tile col (float4)

    float acc[4][4] = {};

    for (int k0 = 0; k0 < 256; k0 += 16) {
        float4 av = *(const float4*)(A + (size_t)(bm + la_r) * DMC + k0 + la_c);
        float4 wv = *(const float4*)(W + (size_t)(k0 + lw_k) * DMC + bn + lw_j);
        As[la_c + 0][la_r] = av.x;
        As[la_c + 1][la_r] = av.y;
        As[la_c + 2][la_r] = av.z;
        As[la_c + 3][la_r] = av.w;
        *(float4*)&Ws[lw_k][lw_j] = wv;
        __syncthreads();
#pragma unroll
        for (int k = 0; k < 16; k++) {
            float4 a4 = *(const float4*)&As[k][ty << 2];
            float4 b4 = *(const float4*)&Ws[k][tx << 2];
            float ar[4] = {a4.x, a4.y, a4.z, a4.w};
            float br[4] = {b4.x, b4.y, b4.z, b4.w};
#pragma unroll
            for (int i = 0; i < 4; i++)
#pragma unroll
                for (int j = 0; j < 4; j++)
                    acc[i][j] = fmaf(ar[i], br[j], acc[i][j]);
        }
        __syncthreads();
    }

    float beta = 1.0f, omb = 0.0f;
    if (mode == 1) {
        float sv = *skipPtr;
        beta = 1.0f / (1.0f + expf(-sv));
        omb = 1.0f - beta;
    }
    float4 bvv = *(const float4*)(bias + bn + (tx << 2));
    float bb[4] = {bvv.x, bvv.y, bvv.z, bvv.w};
#pragma unroll
    for (int i = 0; i < 4; i++) {
        size_t row = (size_t)bm + (ty << 2) + i;
        size_t off = row * DMC + bn + (tx << 2);
        float4 xo = make_float4(0.f, 0.f, 0.f, 0.f);
        if (mode == 1) xo = *(const float4*)(xold + off);
        float xoa[4] = {xo.x, xo.y, xo.z, xo.w};
        float v[4];
#pragma unroll
        for (int j = 0; j < 4; j++) {
            float val = acc[i][j] + bb[j];
            if (mode == 1) val = beta * val + omb * xoa[j];
            if (gelu_after) val = gelu_f(val);
            v[j] = val;
        }
        *(float4*)(C + off) = make_float4(v[0], v[1], v[2], v[3]);
    }
}

// ---------------------------------------------------------------------------
// Edge attention passes. One warp per (edge, head) for dot/scatter.
__global__ void fillneg_kernel(float* __restrict__ buf, int n) {
    int i = blockIdx.x * blockDim.x + threadIdx.x;
    if (i < n) buf[i] = -INFINITY;
}

__global__ void edge_logits_max(const float* __restrict__ q, const float* __restrict__ kt,
                                const int* __restrict__ src, const int* __restrict__ dst,
                                const float* __restrict__ prel,
                                float* __restrict__ logits, float* __restrict__ mbuf) {
    int gid = blockIdx.x * blockDim.x + threadIdx.x;
    int w = gid >> 5;
    int lane = gid & 31;
    if (w >= NEC * NHC) return;
    int e = w >> 2;
    int h = w & 3;
    int sN = src[e], dN = dst[e];
    float2 qa = *(const float2*)(q + (size_t)dN * DMC + h * NDC + lane * 2);
    float2 ka = *(const float2*)(kt + (size_t)sN * DMC + h * NDC + lane * 2);
    float p = qa.x * ka.x + qa.y * ka.y;
#pragma unroll
    for (int o = 16; o > 0; o >>= 1) p += __shfl_xor_sync(0xffffffffu, p, o);
    if (lane == 0) {
        float lg = p * prel[h] * 0.125f;  // / sqrt(64)
        logits[(size_t)e * NHC + h] = lg;
        atomicMaxF(&mbuf[(size_t)dN * NHC + h], lg);
    }
}

__global__ void edge_expsum(const int* __restrict__ dst, float* __restrict__ logits,
                            const float* __restrict__ mbuf, float* __restrict__ sbuf) {
    int i = blockIdx.x * blockDim.x + threadIdx.x;
    if (i >= NEC * NHC) return;
    int e = i >> 2, h = i & 3;
    int dN = dst[e];
    float v = expf(logits[i] - mbuf[(size_t)dN * NHC + h]);
    logits[i] = v;
    atomicAdd(&sbuf[(size_t)dN * NHC + h], v);
}

__global__ void edge_scatter(const int* __restrict__ src, const int* __restrict__ dst,
                             const float* __restrict__ logits, const float* __restrict__ sbuf,
                             const float* __restrict__ vt, float* __restrict__ agg) {
    int gid = blockIdx.x * blockDim.x + threadIdx.x;
    int w = gid >> 5;
    int lane = gid & 31;
    if (w >= NEC * NHC) return;
    int e = w >> 2;
    int h = w & 3;
    int sN = src[e], dN = dst[e];
    float a = logits[(size_t)e * NHC + h] / (sbuf[(size_t)dN * NHC + h] + 1e-16f);
    float2 v = *(const float2*)(vt + (size_t)sN * DMC + h * NDC + lane * 2);
    float* dp = agg + (size_t)dN * DMC + h * NDC + lane * 2;
    atomicAdd(dp + 0, a * v.x);
    atomicAdd(dp + 1, a * v.y);
}

// ---------------------------------------------------------------------------
__global__ void gelu_kernel(float* __restrict__ buf, size_t n4) {
    size_t i = (size_t)blockIdx.x * blockDim.x + threadIdx.x;
    if (i >= n4) return;
    float4 v = ((float4*)buf)[i];
    v.x = gelu_f(v.x); v.y = gelu_f(v.y); v.z = gelu_f(v.z); v.w = gelu_f(v.w);
    ((float4*)buf)[i] = v;
}

// ---------------------------------------------------------------------------
extern "C" void kernel_launch(void* const* d_in, const int* in_sizes, int n_in,
                              void* d_out, int out_size) {
    (void)in_sizes; (void)n_in; (void)out_size;

    float* base = nullptr;
    cudaGetSymbolAddress((void**)&base, g_buf);

    const int*   user_ids  = (const int*)d_in[0];
    const float* x_product = (const float*)d_in[1];
    const int*   edge_src  = (const int*)d_in[2];
    const int*   edge_dst  = (const int*)d_in[3];
    const float* emb       = (const float*)d_in[4];
    const float* Wk        = (const float*)d_in[5];
    const float* bk        = (const float*)d_in[6];
    const float* Wq        = (const float*)d_in[7];
    const float* bq        = (const float*)d_in[8];
    const float* Wv        = (const float*)d_in[9];
    const float* bv        = (const float*)d_in[10];
    const float* Wout      = (const float*)d_in[11];
    const float* bout      = (const float*)d_in[12];
    const float* skipp     = (const float*)d_in[13];
    const float* arel      = (const float*)d_in[14];
    const float* mrel      = (const float*)d_in[15];
    const float* prel      = (const float*)d_in[16];

    float* xuA  = base + OFF_XUA;
    float* xuB  = base + OFF_XUB;
    float* qu   = base + OFF_QU;
    float* ktu  = base + OFF_KTU;
    float* vtu  = base + OFF_VTU;
    float* aggU = base + OFF_AGGU;
    float* xpB  = base + OFF_XPB;
    float* qp   = base + OFF_QP;
    float* ktp  = base + OFF_KTP;
    float* vtp  = base + OFF_VTP;
    float* aggP = base + OFF_AGGP;
    float* logits = base + OFF_LOG;
    float* mbuf = base + OFF_M;
    float* sbuf = base + OFF_S;
    float* Wf   = base + OFF_WF;
    float* bf   = base + OFF_BF;

    float* out_xu = (float*)d_out;
    float* out_xp = (float*)d_out + SZ_U;

    // 1. Precompute fused relation weights + biases
    fuse_w_kernel<<<dim3(8, 256), 256>>>(Wk, Wv, arel, mrel, Wf);
    fuse_b_kernel<<<8, 256>>>(bk, bv, arel, mrel, bf);

    // 2. Gather user embeddings
    {
        size_t n = (size_t)NUC * (DMC / 4);
        gather_kernel<<<(unsigned)((n + 255) / 256), 256>>>(user_ids, emb, xuA);
    }

    const int warps = NEC * NHC;                    // 640,000
    const unsigned blk_w = (unsigned)(((size_t)warps * 32 + 255) / 256);
    const unsigned blk_t = (unsigned)((warps + 255) / 256);

    for (int l = 0; l < 2; l++) {
        const float* xu_in = l ? xuB : xuA;
        const float* xp_in = l ? xpB : x_product;
        float* xu_out = l ? out_xu : xuB;
        float* xp_out = l ? out_xp : xpB;
        int gelu_after = (l == 0) ? 1 : 0;

        // Projections (fused relation transforms folded into weights)
        // user-side (M = NU): q (plain Wq), kt (Wf[0*4+l*2+0]), vt (Wf[1*4+l*2+0])
        {
            dim3 gU(4, NUC / 64), gP(4, NPC / 64);
            gemm_kernel<<<gU, 256>>>(xu_in, Wq + (size_t)(l * 2 + 0) * DMC * DMC,
                                     bq + (size_t)(l * 2 + 0) * DMC, qu, 0, nullptr, nullptr, 0);
            gemm_kernel<<<gU, 256>>>(xu_in, Wf + (size_t)(0 * 4 + l * 2 + 0) * DMC * DMC,
                                     bf + (size_t)(0 * 4 + l * 2 + 0) * DMC, ktu, 0, nullptr, nullptr, 0);
            gemm_kernel<<<gU, 256>>>(xu_in, Wf + (size_t)(1 * 4 + l * 2 + 0) * DMC * DMC,
                                     bf + (size_t)(1 * 4 + l * 2 + 0) * DMC, vtu, 0, nullptr, nullptr, 0);
            gemm_kernel<<<gP, 256>>>(xp_in, Wq + (size_t)(l * 2 + 1) * DMC * DMC,
                                     bq + (size_t)(l * 2 + 1) * DMC, qp, 0, nullptr, nullptr, 0);
            gemm_kernel<<<gP, 256>>>(xp_in, Wf + (size_t)(0 * 4 + l * 2 + 1) * DMC * DMC,
                                     bf + (size_t)(0 * 4 + l * 2 + 1) * DMC, ktp, 0, nullptr, nullptr, 0);
            gemm_kernel<<<gP, 256>>>(xp_in, Wf + (size_t)(1 * 4 + l * 2 + 1) * DMC * DMC,
                                     bf + (size_t)(1 * 4 + l * 2 + 1) * DMC, vtp, 0, nullptr, nullptr, 0);
        }

        // rel 0: user -> product (dst = product)
        {
            int n = NPC * NHC;
            fillneg_kernel<<<(n + 255) / 256, 256>>>(mbuf, n);
            cudaMemsetAsync(sbuf, 0, (size_t)n * sizeof(float));
            cudaMemsetAsync(aggP, 0, SZ_P * sizeof(float));
            edge_logits_max<<<blk_w, 256>>>(qp, ktu, edge_src, edge_dst,
                                            prel + (size_t)(l * 2 + 0) * NHC, logits, mbuf);
            edge_expsum<<<blk_t, 256>>>(edge_dst, logits, mbuf, sbuf);
            edge_scatter<<<blk_w, 256>>>(edge_src, edge_dst, logits, sbuf, vtu, aggP);
        }

        // rel 1: product -> user (dst = user; src/dst arrays swapped)
        {
            int n = NUC * NHC;
            fillneg_kernel<<<(n + 255) / 256, 256>>>(mbuf, n);
            cudaMemsetAsync(sbuf, 0, (size_t)n * sizeof(float));
            cudaMemsetAsync(aggU, 0, SZ_U * sizeof(float));
            edge_logits_max<<<blk_w, 256>>>(qu, ktp, edge_dst, edge_src,
                                            prel + (size_t)(l * 2 + 1) * NHC, logits, mbuf);
            edge_expsum<<<blk_t, 256>>>(edge_src, logits, mbuf, sbuf);
            edge_scatter<<<blk_w, 256>>>(edge_dst, edge_src, logits, sbuf, vtp, aggU);
        }

        // GELU on aggregates (input to Wout)
        gelu_kernel<<<(unsigned)((SZ_P / 4 + 255) / 256), 256>>>(aggP, SZ_P / 4);
        gelu_kernel<<<(unsigned)((SZ_U / 4 + 255) / 256), 256>>>(aggU, SZ_U / 4);

        // Output GEMMs with skip blend (+ inter-layer gelu fused for l==0)
        {
            dim3 gU(4, NUC / 64), gP(4, NPC / 64);
            gemm_kernel<<<gP, 256>>>(aggP, Wout + (size_t)(l * 2 + 1) * DMC * DMC,
                                     bout + (size_t)(l * 2 + 1) * DMC, xp_out,
                                     1, xp_in, skipp + (l * 2 + 1), gelu_after);
            gemm_kernel<<<gU, 256>>>(aggU, Wout + (size_t)(l * 2 + 0) * DMC * DMC,
                                     bout + (size_t)(l * 2 + 0) * DMC, xu_out,
                                     1, xu_in, skipp + (l * 2 + 0), gelu_after);
        }
    }
}

// round 2
// speedup vs baseline: 2.0823x; 2.0823x over previous
#include <cuda_runtime.h>
#include <math.h>
#include <stdint.h>

// Problem constants
#define NUC 80000
#define NPC 40000
#define NEC 160000
#define DMC 256
#define NHC 4
#define NDC 64
#define LDPROJ 768

static const size_t SZ_U = (size_t)NUC * DMC;   // 20,480,000
static const size_t SZ_P = (size_t)NPC * DMC;   // 10,240,000

// Scratch layout (floats)
static const size_t OFF_XUA   = 0;
static const size_t OFF_XUB   = SZ_U;
static const size_t OFF_PROJU = 2 * SZ_U;                    // NU*768
static const size_t OFF_AGGU  = 5 * SZ_U;
static const size_t OFF_XPB   = 6 * SZ_U;
static const size_t OFF_PROJP = OFF_XPB + SZ_P;              // NP*768
static const size_t OFF_AGGP  = OFF_XPB + 4 * SZ_P;
static const size_t OFF_LOG   = OFF_XPB + 5 * SZ_P;          // E*H
static const size_t OFF_M     = OFF_LOG + (size_t)NEC * NHC;
static const size_t OFF_S     = OFF_M + (size_t)NUC * NHC;
static const size_t OFF_WBIG  = OFF_S + (size_t)NUC * NHC;   // 4 * 256*768
static const size_t OFF_BBIG  = OFF_WBIG + (size_t)4 * DMC * LDPROJ;
static const size_t TOTAL_F   = OFF_BBIG + 4 * LDPROJ;

__device__ float g_buf[TOTAL_F];

// ---------------------------------------------------------------------------
__device__ __forceinline__ float gelu_f(float x) {
    return 0.5f * x * (1.0f + erff(x * 0.70710678118654752f));
}

__device__ __forceinline__ void atomicMaxF(float* addr, float v) {
    if (v >= 0.0f) atomicMax((int*)addr, __float_as_int(v));
    else           atomicMin((unsigned int*)addr, __float_as_uint(v));
}

__device__ __forceinline__ uint32_t f2tf(float f) {
    uint32_t u;
    asm("cvt.rna.tf32.f32 %0, %1;" : "=r"(u) : "f"(f));
    return u;
}

// ---------------------------------------------------------------------------
// Assemble Wbig[c][256][768] = [ Wq | Wk@arel | Wv@mrel ]  (c = l*2 + t)
__global__ void copyq_kernel(const float* __restrict__ Wq, const float* __restrict__ bq,
                             float* __restrict__ Wbig, float* __restrict__ bbig) {
    int c = blockIdx.x;    // 0..3
    int i = blockIdx.y;    // 0..255
    int j = threadIdx.x;   // 0..255
    Wbig[(size_t)c * DMC * LDPROJ + (size_t)i * LDPROJ + j] = Wq[(size_t)c * DMC * DMC + (size_t)i * DMC + j];
    if (i == 0) bbig[(size_t)c * LDPROJ + j] = bq[(size_t)c * DMC + j];
}

__global__ void fuse_w_kernel(const float* __restrict__ Wk, const float* __restrict__ Wv,
                              const float* __restrict__ arel, const float* __restrict__ mrel,
                              float* __restrict__ Wbig) {
    int c = blockIdx.x;        // 0..7
    int i = blockIdx.y;        // 0..255
    int j = threadIdx.x;       // 0..255
    int kv = c >> 2;
    int lt = c & 3;
    const float* Wsrc = (kv ? Wv : Wk) + (size_t)lt * DMC * DMC;
    const float* R    = (kv ? mrel : arel) + (size_t)lt * NHC * NDC * NDC;
    int h = j >> 6, e = j & 63;
    const float* wrow = Wsrc + (size_t)i * DMC + h * NDC;
    const float* rr   = R + (size_t)h * NDC * NDC + e;
    float sum = 0.0f;
#pragma unroll 8
    for (int d = 0; d < NDC; d++) sum = fmaf(wrow[d], rr[(size_t)d * NDC], sum);
    Wbig[(size_t)lt * DMC * LDPROJ + (size_t)i * LDPROJ + DMC + kv * DMC + j] = sum;
}

__global__ void fuse_b_kernel(const float* __restrict__ bk, const float* __restrict__ bv,
                              const float* __restrict__ arel, const float* __restrict__ mrel,
                              float* __restrict__ bbig) {
    int c = blockIdx.x;        // 0..7
    int j = threadIdx.x;       // 0..255
    int kv = c >> 2;
    int lt = c & 3;
    const float* bsrc = (kv ? bv : bk) + (size_t)lt * DMC;
    const float* R    = (kv ? mrel : arel) + (size_t)lt * NHC * NDC * NDC;
    int h = j >> 6, e = j & 63;
    float sum = 0.0f;
#pragma unroll 8
    for (int d = 0; d < NDC; d++)
        sum = fmaf(bsrc[h * NDC + d], R[(size_t)h * NDC * NDC + (size_t)d * NDC + e], sum);
    bbig[(size_t)lt * LDPROJ + DMC + kv * DMC + j] = sum;
}

// ---------------------------------------------------------------------------
__global__ void gather_kernel(const int* __restrict__ ids, const float* __restrict__ tab,
                              float* __restrict__ out) {
    size_t i = (size_t)blockIdx.x * blockDim.x + threadIdx.x;
    if (i >= (size_t)NUC * (DMC / 4)) return;
    size_t row = i >> 6;
    int c4 = (int)(i & 63);
    ((float4*)out)[i] = ((const float4*)(tab + (size_t)ids[row] * DMC))[c4];
}

// ---------------------------------------------------------------------------
// TF32 tensor-core GEMM: C[M,N] = A[M,256] @ W[256,N] + bias
// Block tile 64(M) x 128(N), BK=16, 256 threads (8 warps of 32x32 warp tiles).
// mode 1: C = beta*(AW+b) + (1-beta)*xold (ld 256), beta = sigmoid(*skipPtr)
__global__ __launch_bounds__(256)
void gemm_tf32(const float* __restrict__ A, int lda,
               const float* __restrict__ W, int ldw,
               const float* __restrict__ bias,
               float* __restrict__ C, int ldc,
               int mode, const float* __restrict__ xold,
               const float* __restrict__ skipPtr, int gelu_after) {
    __shared__ uint32_t As[64][20];    // padded: conflict-free fragment loads
    __shared__ uint32_t Bs[16][136];

    const int bm = blockIdx.y * 64;
    const int bn = blockIdx.x * 128;
    const int t  = threadIdx.x;
    const int warp = t >> 5;
    const int lane = t & 31;
    const int wm = warp >> 2;          // 0..1
    const int wn = warp & 3;           // 0..3
    const int lr = lane >> 2;          // 0..7
    const int lc = lane & 3;           // 0..3

    // global-load coords
    const int ga_r = t >> 2;           // 0..63
    const int ga_c = (t & 3) << 2;     // 0,4,8,12
    const int gb_k = t >> 5;           // 0..7
    const int gb_c = (t & 31) << 2;    // 0..124*? (0..124)

    float c[2][4][4];
#pragma unroll
    for (int mi = 0; mi < 2; mi++)
#pragma unroll
        for (int ni = 0; ni < 4; ni++)
#pragma unroll
            for (int r = 0; r < 4; r++) c[mi][ni][r] = 0.0f;

    for (int k0 = 0; k0 < 256; k0 += 16) {
        // load A tile 64x16
        {
            float4 av = *(const float4*)(A + (size_t)(bm + ga_r) * lda + k0 + ga_c);
            As[ga_r][ga_c + 0] = f2tf(av.x);
            As[ga_r][ga_c + 1] = f2tf(av.y);
            As[ga_r][ga_c + 2] = f2tf(av.z);
            As[ga_r][ga_c + 3] = f2tf(av.w);
        }
        // load B tile 16x128 (two k-rows per thread)
        {
            float4 w0 = *(const float4*)(W + (size_t)(k0 + gb_k) * ldw + bn + gb_c);
            float4 w1 = *(const float4*)(W + (size_t)(k0 + gb_k + 8) * ldw + bn + gb_c);
            Bs[gb_k][gb_c + 0] = f2tf(w0.x);
            Bs[gb_k][gb_c + 1] = f2tf(w0.y);
            Bs[gb_k][gb_c + 2] = f2tf(w0.z);
            Bs[gb_k][gb_c + 3] = f2tf(w0.w);
            Bs[gb_k + 8][gb_c + 0] = f2tf(w1.x);
            Bs[gb_k + 8][gb_c + 1] = f2tf(w1.y);
            Bs[gb_k + 8][gb_c + 2] = f2tf(w1.z);
            Bs[gb_k + 8][gb_c + 3] = f2tf(w1.w);
        }
        __syncthreads();

#pragma unroll
        for (int ks = 0; ks < 2; ks++) {
            const int kb = ks << 3;
            uint32_t a[2][4], b[4][2];
#pragma unroll
            for (int mi = 0; mi < 2; mi++) {
                int row = wm * 32 + mi * 16 + lr;
                a[mi][0] = As[row][kb + lc];
                a[mi][1] = As[row + 8][kb + lc];
                a[mi][2] = As[row][kb + lc + 4];
                a[mi][3] = As[row + 8][kb + lc + 4];
            }
#pragma unroll
            for (int ni = 0; ni < 4; ni++) {
                int col = wn * 32 + ni * 8 + lr;
                b[ni][0] = Bs[kb + lc][col];
                b[ni][1] = Bs[kb + lc + 4][col];
            }
#pragma unroll
            for (int mi = 0; mi < 2; mi++)
#pragma unroll
                for (int ni = 0; ni < 4; ni++) {
                    asm volatile(
                        "mma.sync.aligned.m16n8k8.row.col.f32.tf32.tf32.f32 "
                        "{%0,%1,%2,%3}, {%4,%5,%6,%7}, {%8,%9}, {%0,%1,%2,%3};"
                        : "+f"(c[mi][ni][0]), "+f"(c[mi][ni][1]),
                          "+f"(c[mi][ni][2]), "+f"(c[mi][ni][3])
                        : "r"(a[mi][0]), "r"(a[mi][1]), "r"(a[mi][2]), "r"(a[mi][3]),
                          "r"(b[ni][0]), "r"(b[ni][1]));
                }
        }
        __syncthreads();
    }

    float beta = 1.0f, omb = 0.0f;
    if (mode == 1) {
        float sv = *skipPtr;
        beta = 1.0f / (1.0f + expf(-sv));
        omb = 1.0f - beta;
    }

#pragma unroll
    for (int mi = 0; mi < 2; mi++) {
#pragma unroll
        for (int ni = 0; ni < 4; ni++) {
            int row0 = bm + wm * 32 + mi * 16 + lr;
            int col  = bn + wn * 32 + ni * 8 + (lc << 1);
            float b0 = bias[col], b1 = bias[col + 1];
#pragma unroll
            for (int half = 0; half < 2; half++) {
                int row = row0 + half * 8;
                float v0 = c[mi][ni][half * 2 + 0] + b0;
                float v1 = c[mi][ni][half * 2 + 1] + b1;
                if (mode == 1) {
                    float2 xo = *(const float2*)(xold + (size_t)row * DMC + col);
                    v0 = beta * v0 + omb * xo.x;
                    v1 = beta * v1 + omb * xo.y;
                }
                if (gelu_after) { v0 = gelu_f(v0); v1 = gelu_f(v1); }
                *(float2*)(C + (size_t)row * ldc + col) = make_float2(v0, v1);
            }
        }
    }
}

// ---------------------------------------------------------------------------
// Edge attention passes (q/kt/vt live in proj buffers with stride 768)
__global__ void fillneg_kernel(float* __restrict__ buf, int n) {
    int i = blockIdx.x * blockDim.x + threadIdx.x;
    if (i < n) buf[i] = -INFINITY;
}

__global__ void edge_logits_max(const float* __restrict__ q, const float* __restrict__ kt,
                                const int* __restrict__ src, const int* __restrict__ dst,
                                const float* __restrict__ prel,
                                float* __restrict__ logits, float* __restrict__ mbuf) {
    int gid = blockIdx.x * blockDim.x + threadIdx.x;
    int w = gid >> 5;
    int lane = gid & 31;
    if (w >= NEC * NHC) return;
    int e = w >> 2;
    int h = w & 3;
    int sN = src[e], dN = dst[e];
    float2 qa = *(const float2*)(q + (size_t)dN * LDPROJ + h * NDC + lane * 2);
    float2 ka = *(const float2*)(kt + (size_t)sN * LDPROJ + h * NDC + lane * 2);
    float p = qa.x * ka.x + qa.y * ka.y;
#pragma unroll
    for (int o = 16; o > 0; o >>= 1) p += __shfl_xor_sync(0xffffffffu, p, o);
    if (lane == 0) {
        float lg = p * prel[h] * 0.125f;
        logits[(size_t)e * NHC + h] = lg;
        atomicMaxF(&mbuf[(size_t)dN * NHC + h], lg);
    }
}

__global__ void edge_expsum(const int* __restrict__ dst, float* __restrict__ logits,
                            const float* __restrict__ mbuf, float* __restrict__ sbuf) {
    int i = blockIdx.x * blockDim.x + threadIdx.x;
    if (i >= NEC * NHC) return;
    int e = i >> 2, h = i & 3;
    int dN = dst[e];
    float v = expf(logits[i] - mbuf[(size_t)dN * NHC + h]);
    logits[i] = v;
    atomicAdd(&sbuf[(size_t)dN * NHC + h], v);
}

__global__ void edge_scatter(const int* __restrict__ src, const int* __restrict__ dst,
                             const float* __restrict__ logits, const float* __restrict__ sbuf,
                             const float* __restrict__ vt, float* __restrict__ agg) {
    int gid = blockIdx.x * blockDim.x + threadIdx.x;
    int w = gid >> 5;
    int lane = gid & 31;
    if (w >= NEC * NHC) return;
    int e = w >> 2;
    int h = w & 3;
    int sN = src[e], dN = dst[e];
    float a = logits[(size_t)e * NHC + h] / (sbuf[(size_t)dN * NHC + h] + 1e-16f);
    float2 v = *(const float2*)(vt + (size_t)sN * LDPROJ + h * NDC + lane * 2);
    float* dp = agg + (size_t)dN * DMC + h * NDC + lane * 2;
    atomicAdd(dp + 0, a * v.x);
    atomicAdd(dp + 1, a * v.y);
}

// ---------------------------------------------------------------------------
__global__ void gelu_kernel(float* __restrict__ buf, size_t n4) {
    size_t i = (size_t)blockIdx.x * blockDim.x + threadIdx.x;
    if (i >= n4) return;
    float4 v = ((float4*)buf)[i];
    v.x = gelu_f(v.x); v.y = gelu_f(v.y); v.z = gelu_f(v.z); v.w = gelu_f(v.w);
    ((float4*)buf)[i] = v;
}

// ---------------------------------------------------------------------------
extern "C" void kernel_launch(void* const* d_in, const int* in_sizes, int n_in,
                              void* d_out, int out_size) {
    (void)in_sizes; (void)n_in; (void)out_size;

    float* base = nullptr;
    cudaGetSymbolAddress((void**)&base, g_buf);

    const int*   user_ids  = (const int*)d_in[0];
    const float* x_product = (const float*)d_in[1];
    const int*   edge_src  = (const int*)d_in[2];
    const int*   edge_dst  = (const int*)d_in[3];
    const float* emb       = (const float*)d_in[4];
    const float* Wk        = (const float*)d_in[5];
    const float* bk        = (const float*)d_in[6];
    const float* Wq        = (const float*)d_in[7];
    const float* bq        = (const float*)d_in[8];
    const float* Wv        = (const float*)d_in[9];
    const float* bv        = (const float*)d_in[10];
    const float* Wout      = (const float*)d_in[11];
    const float* bout      = (const float*)d_in[12];
    const float* skipp     = (const float*)d_in[13];
    const float* arel      = (const float*)d_in[14];
    const float* mrel      = (const float*)d_in[15];
    const float* prel      = (const float*)d_in[16];

    float* xuA   = base + OFF_XUA;
    float* xuB   = base + OFF_XUB;
    float* projU = base + OFF_PROJU;
    float* aggU  = base + OFF_AGGU;
    float* xpB   = base + OFF_XPB;
    float* projP = base + OFF_PROJP;
    float* aggP  = base + OFF_AGGP;
    float* logits = base + OFF_LOG;
    float* mbuf  = base + OFF_M;
    float* sbuf  = base + OFF_S;
    float* Wbig  = base + OFF_WBIG;
    float* bbig  = base + OFF_BBIG;

    float* out_xu = (float*)d_out;
    float* out_xp = (float*)d_out + SZ_U;

    // 1. Assemble fused projection weights [Wq | Wk@arel | Wv@mrel]
    copyq_kernel<<<dim3(4, 256), 256>>>(Wq, bq, Wbig, bbig);
    fuse_w_kernel<<<dim3(8, 256), 256>>>(Wk, Wv, arel, mrel, Wbig);
    fuse_b_kernel<<<8, 256>>>(bk, bv, arel, mrel, bbig);

    // 2. Gather user embeddings
    {
        size_t n = (size_t)NUC * (DMC / 4);
        gather_kernel<<<(unsigned)((n + 255) / 256), 256>>>(user_ids, emb, xuA);
    }

    const int warps = NEC * NHC;
    const unsigned blk_w = (unsigned)(((size_t)warps * 32 + 255) / 256);
    const unsigned blk_t = (unsigned)((warps + 255) / 256);

    for (int l = 0; l < 2; l++) {
        const float* xu_in = l ? xuB : xuA;
        const float* xp_in = l ? xpB : x_product;
        float* xu_out = l ? out_xu : xuB;
        float* xp_out = l ? out_xp : xpB;
        int gelu_after = (l == 0) ? 1 : 0;

        // Projections: one [M,256]x[256,768] GEMM per node type
        {
            size_t cu = (size_t)(l * 2 + 0), cp = (size_t)(l * 2 + 1);
            gemm_tf32<<<dim3(6, NUC / 64), 256>>>(
                xu_in, DMC, Wbig + cu * DMC * LDPROJ, LDPROJ, bbig + cu * LDPROJ,
                projU, LDPROJ, 0, nullptr, nullptr, 0);
            gemm_tf32<<<dim3(6, NPC / 64), 256>>>(
                xp_in, DMC, Wbig + cp * DMC * LDPROJ, LDPROJ, bbig + cp * LDPROJ,
                projP, LDPROJ, 0, nullptr, nullptr, 0);
        }

        // rel 0: user -> product (dst = product)
        {
            int n = NPC * NHC;
            fillneg_kernel<<<(n + 255) / 256, 256>>>(mbuf, n);
            cudaMemsetAsync(sbuf, 0, (size_t)n * sizeof(float));
            cudaMemsetAsync(aggP, 0, SZ_P * sizeof(float));
            edge_logits_max<<<blk_w, 256>>>(projP /*q*/, projU + DMC /*kt*/,
                                            edge_src, edge_dst,
                                            prel + (size_t)(l * 2 + 0) * NHC, logits, mbuf);
            edge_expsum<<<blk_t, 256>>>(edge_dst, logits, mbuf, sbuf);
            edge_scatter<<<blk_w, 256>>>(edge_src, edge_dst, logits, sbuf,
                                         projU + 2 * DMC /*vt*/, aggP);
        }

        // rel 1: product -> user (dst = user)
        {
            int n = NUC * NHC;
            fillneg_kernel<<<(n + 255) / 256, 256>>>(mbuf, n);
            cudaMemsetAsync(sbuf, 0, (size_t)n * sizeof(float));
            cudaMemsetAsync(aggU, 0, SZ_U * sizeof(float));
            edge_logits_max<<<blk_w, 256>>>(projU /*q*/, projP + DMC /*kt*/,
                                            edge_dst, edge_src,
                                            prel + (size_t)(l * 2 + 1) * NHC, logits, mbuf);
            edge_expsum<<<blk_t, 256>>>(edge_src, logits, mbuf, sbuf);
            edge_scatter<<<blk_w, 256>>>(edge_dst, edge_src, logits, sbuf,
                                         projP + 2 * DMC /*vt*/, aggU);
        }

        // GELU on aggregates (input to Wout)
        gelu_kernel<<<(unsigned)((SZ_P / 4 + 255) / 256), 256>>>(aggP, SZ_P / 4);
        gelu_kernel<<<(unsigned)((SZ_U / 4 + 255) / 256), 256>>>(aggU, SZ_U / 4);

        // Output GEMMs with skip blend (+ inter-layer gelu fused for l==0)
        {
            gemm_tf32<<<dim3(2, NPC / 64), 256>>>(
                aggP, DMC, Wout + (size_t)(l * 2 + 1) * DMC * DMC, DMC,
                bout + (size_t)(l * 2 + 1) * DMC, xp_out, DMC,
                1, xp_in, skipp + (l * 2 + 1), gelu_after);
            gemm_tf32<<<dim3(2, NUC / 64), 256>>>(
                aggU, DMC, Wout + (size_t)(l * 2 + 0) * DMC * DMC, DMC,
                bout + (size_t)(l * 2 + 0) * DMC, xu_out, DMC,
                1, xu_in, skipp + (l * 2 + 0), gelu_after);
        }
    }
}

// round 3
// speedup vs baseline: 2.4076x; 1.1562x over previous
#include <cuda_runtime.h>
#include <math.h>
#include <stdint.h>

// Problem constants
#define NUC 80000
#define NPC 40000
#define NEC 160000
#define DMC 256
#define NHC 4
#define NDC 64
#define LDPROJ 768

static const size_t SZ_U = (size_t)NUC * DMC;
static const size_t SZ_P = (size_t)NPC * DMC;

// Scratch layout (floats)
static const size_t OFF_XUA   = 0;
static const size_t OFF_XUB   = SZ_U;
static const size_t OFF_PROJU = 2 * SZ_U;                    // NU*768
static const size_t OFF_AGGU  = 5 * SZ_U;
static const size_t OFF_XPB   = 6 * SZ_U;
static const size_t OFF_PROJP = OFF_XPB + SZ_P;              // NP*768
static const size_t OFF_AGGP  = OFF_XPB + 4 * SZ_P;
static const size_t OFF_WBIG  = OFF_XPB + 5 * SZ_P;          // 4 * 256*768
static const size_t OFF_BBIG  = OFF_WBIG + (size_t)4 * DMC * LDPROJ;
static const size_t OFF_INT   = OFF_BBIG + 4 * LDPROJ;
// int scratch (1 float slot = 1 int):
//   rowptrP[NP+1], rowptrU[NU+1], degP[NP], degU[NU],
//   curP[NP], curU[NU], colP[E], colU[E]
static const size_t I_ROWP = 0;
static const size_t I_ROWU = I_ROWP + NPC + 1;
static const size_t I_DEGP = I_ROWU + NUC + 1;
static const size_t I_DEGU = I_DEGP + NPC;
static const size_t I_CURP = I_DEGU + NUC;
static const size_t I_CURU = I_CURP + NPC;
static const size_t I_COLP = I_CURU + NUC;
static const size_t I_COLU = I_COLP + NEC;
static const size_t N_INTS = I_COLU + NEC;
static const size_t TOTAL_F = OFF_INT + N_INTS;

__device__ float g_buf[TOTAL_F];

// ---------------------------------------------------------------------------
__device__ __forceinline__ float gelu_f(float x) {
    return 0.5f * x * (1.0f + erff(x * 0.70710678118654752f));
}

__device__ __forceinline__ uint32_t f2tf(float f) {
    uint32_t u;
    asm("cvt.rna.tf32.f32 %0, %1;" : "=r"(u) : "f"(f));
    return u;
}

// ---------------------------------------------------------------------------
// Assemble Wbig[c][256][768] = [ Wq | Wk@arel | Wv@mrel ]  (c = l*2 + t)
__global__ void copyq_kernel(const float* __restrict__ Wq, const float* __restrict__ bq,
                             float* __restrict__ Wbig, float* __restrict__ bbig) {
    int c = blockIdx.x, i = blockIdx.y, j = threadIdx.x;
    Wbig[(size_t)c * DMC * LDPROJ + (size_t)i * LDPROJ + j] = Wq[(size_t)c * DMC * DMC + (size_t)i * DMC + j];
    if (i == 0) bbig[(size_t)c * LDPROJ + j] = bq[(size_t)c * DMC + j];
}

__global__ void fuse_w_kernel(const float* __restrict__ Wk, const float* __restrict__ Wv,
                              const float* __restrict__ arel, const float* __restrict__ mrel,
                              float* __restrict__ Wbig) {
    int c = blockIdx.x, i = blockIdx.y, j = threadIdx.x;
    int kv = c >> 2;
    int lt = c & 3;
    const float* Wsrc = (kv ? Wv : Wk) + (size_t)lt * DMC * DMC;
    const float* R    = (kv ? mrel : arel) + (size_t)lt * NHC * NDC * NDC;
    int h = j >> 6, e = j & 63;
    const float* wrow = Wsrc + (size_t)i * DMC + h * NDC;
    const float* rr   = R + (size_t)h * NDC * NDC + e;
    float sum = 0.0f;
#pragma unroll 8
    for (int d = 0; d < NDC; d++) sum = fmaf(wrow[d], rr[(size_t)d * NDC], sum);
    Wbig[(size_t)lt * DMC * LDPROJ + (size_t)i * LDPROJ + DMC + kv * DMC + j] = sum;
}

__global__ void fuse_b_kernel(const float* __restrict__ bk, const float* __restrict__ bv,
                              const float* __restrict__ arel, const float* __restrict__ mrel,
                              float* __restrict__ bbig) {
    int c = blockIdx.x, j = threadIdx.x;
    int kv = c >> 2;
    int lt = c & 3;
    const float* bsrc = (kv ? bv : bk) + (size_t)lt * DMC;
    const float* R    = (kv ? mrel : arel) + (size_t)lt * NHC * NDC * NDC;
    int h = j >> 6, e = j & 63;
    float sum = 0.0f;
#pragma unroll 8
    for (int d = 0; d < NDC; d++)
        sum = fmaf(bsrc[h * NDC + d], R[(size_t)h * NDC * NDC + (size_t)d * NDC + e], sum);
    bbig[(size_t)lt * LDPROJ + DMC + kv * DMC + j] = sum;
}

// ---------------------------------------------------------------------------
__global__ void gather_kernel(const int* __restrict__ ids, const float* __restrict__ tab,
                              float* __restrict__ out) {
    size_t i = (size_t)blockIdx.x * blockDim.x + threadIdx.x;
    if (i >= (size_t)NUC * (DMC / 4)) return;
    size_t row = i >> 6;
    int c4 = (int)(i & 63);
    ((float4*)out)[i] = ((const float4*)(tab + (size_t)ids[row] * DMC))[c4];
}

// ---------------------------------------------------------------------------
// CSR construction
__global__ void count_deg(const int* __restrict__ src, const int* __restrict__ dst,
                          int* __restrict__ degP, int* __restrict__ degU) {
    int e = blockIdx.x * blockDim.x + threadIdx.x;
    if (e >= NEC) return;
    atomicAdd(&degP[dst[e]], 1);
    atomicAdd(&degU[src[e]], 1);
}

// Single-block exclusive scan: rowptr[i] = prefix, rowptr[n] = total; cursor = copy.
__global__ __launch_bounds__(1024)
void scan_kernel(const int* __restrict__ deg, int* __restrict__ rowptr,
                 int* __restrict__ cursor, int n) {
    __shared__ int wsums[32];
    int t = threadIdx.x;
    int lane = t & 31, wid = t >> 5;
    int C = (n + 1023) / 1024;
    int start = t * C; if (start > n) start = n;
    int end = start + C; if (end > n) end = n;
    int s = 0;
    for (int i = start; i < end; i++) s += deg[i];
    int v = s;
#pragma unroll
    for (int o = 1; o < 32; o <<= 1) {
        int u = __shfl_up_sync(0xffffffffu, v, o);
        if (lane >= o) v += u;
    }
    if (lane == 31) wsums[wid] = v;
    __syncthreads();
    if (wid == 0) {
        int wv = wsums[lane];
#pragma unroll
        for (int o = 1; o < 32; o <<= 1) {
            int u = __shfl_up_sync(0xffffffffu, wv, o);
            if (lane >= o) wv += u;
        }
        wsums[lane] = wv;
    }
    __syncthreads();
    int warp_off = (wid > 0) ? wsums[wid - 1] : 0;
    int run = warp_off + v - s;
    for (int i = start; i < end; i++) {
        rowptr[i] = run;
        cursor[i] = run;
        run += deg[i];
    }
    if (t == 0) rowptr[n] = wsums[31];
}

__global__ void build_csr(const int* __restrict__ src, const int* __restrict__ dst,
                          int* __restrict__ curP, int* __restrict__ curU,
                          int* __restrict__ colP, int* __restrict__ colU) {
    int e = blockIdx.x * blockDim.x + threadIdx.x;
    if (e >= NEC) return;
    int s = src[e], d = dst[e];
    colP[atomicAdd(&curP[d], 1)] = s;
    colU[atomicAdd(&curU[s], 1)] = d;
}

// ---------------------------------------------------------------------------
// TF32 tensor-core GEMM (unchanged from R2)
__global__ __launch_bounds__(256)
void gemm_tf32(const float* __restrict__ A, int lda,
               const float* __restrict__ W, int ldw,
               const float* __restrict__ bias,
               float* __restrict__ C, int ldc,
               int mode, const float* __restrict__ xold,
               const float* __restrict__ skipPtr, int gelu_after) {
    __shared__ uint32_t As[64][20];
    __shared__ uint32_t Bs[16][136];

    const int bm = blockIdx.y * 64;
    const int bn = blockIdx.x * 128;
    const int t  = threadIdx.x;
    const int warp = t >> 5;
    const int lane = t & 31;
    const int wm = warp >> 2;
    const int wn = warp & 3;
    const int lr = lane >> 2;
    const int lc = lane & 3;

    const int ga_r = t >> 2;
    const int ga_c = (t & 3) << 2;
    const int gb_k = t >> 5;
    const int gb_c = (t & 31) << 2;

    float c[2][4][4];
#pragma unroll
    for (int mi = 0; mi < 2; mi++)
#pragma unroll
        for (int ni = 0; ni < 4; ni++)
#pragma unroll
            for (int r = 0; r < 4; r++) c[mi][ni][r] = 0.0f;

    for (int k0 = 0; k0 < 256; k0 += 16) {
        {
            float4 av = *(const float4*)(A + (size_t)(bm + ga_r) * lda + k0 + ga_c);
            As[ga_r][ga_c + 0] = f2tf(av.x);
            As[ga_r][ga_c + 1] = f2tf(av.y);
            As[ga_r][ga_c + 2] = f2tf(av.z);
            As[ga_r][ga_c + 3] = f2tf(av.w);
        }
        {
            float4 w0 = *(const float4*)(W + (size_t)(k0 + gb_k) * ldw + bn + gb_c);
            float4 w1 = *(const float4*)(W + (size_t)(k0 + gb_k + 8) * ldw + bn + gb_c);
            Bs[gb_k][gb_c + 0] = f2tf(w0.x);
            Bs[gb_k][gb_c + 1] = f2tf(w0.y);
            Bs[gb_k][gb_c + 2] = f2tf(w0.z);
            Bs[gb_k][gb_c + 3] = f2tf(w0.w);
            Bs[gb_k + 8][gb_c + 0] = f2tf(w1.x);
            Bs[gb_k + 8][gb_c + 1] = f2tf(w1.y);
            Bs[gb_k + 8][gb_c + 2] = f2tf(w1.z);
            Bs[gb_k + 8][gb_c + 3] = f2tf(w1.w);
        }
        __syncthreads();

#pragma unroll
        for (int ks = 0; ks < 2; ks++) {
            const int kb = ks << 3;
            uint32_t a[2][4], b[4][2];
#pragma unroll
            for (int mi = 0; mi < 2; mi++) {
                int row = wm * 32 + mi * 16 + lr;
                a[mi][0] = As[row][kb + lc];
                a[mi][1] = As[row + 8][kb + lc];
                a[mi][2] = As[row][kb + lc + 4];
                a[mi][3] = As[row + 8][kb + lc + 4];
            }
#pragma unroll
            for (int ni = 0; ni < 4; ni++) {
                int col = wn * 32 + ni * 8 + lr;
                b[ni][0] = Bs[kb + lc][col];
                b[ni][1] = Bs[kb + lc + 4][col];
            }
#pragma unroll
            for (int mi = 0; mi < 2; mi++)
#pragma unroll
                for (int ni = 0; ni < 4; ni++) {
                    asm volatile(
                        "mma.sync.aligned.m16n8k8.row.col.f32.tf32.tf32.f32 "
                        "{%0,%1,%2,%3}, {%4,%5,%6,%7}, {%8,%9}, {%0,%1,%2,%3};"
                        : "+f"(c[mi][ni][0]), "+f"(c[mi][ni][1]),
                          "+f"(c[mi][ni][2]), "+f"(c[mi][ni][3])
                        : "r"(a[mi][0]), "r"(a[mi][1]), "r"(a[mi][2]), "r"(a[mi][3]),
                          "r"(b[ni][0]), "r"(b[ni][1]));
                }
        }
        __syncthreads();
    }

    float beta = 1.0f, omb = 0.0f;
    if (mode == 1) {
        float sv = *skipPtr;
        beta = 1.0f / (1.0f + expf(-sv));
        omb = 1.0f - beta;
    }

#pragma unroll
    for (int mi = 0; mi < 2; mi++) {
#pragma unroll
        for (int ni = 0; ni < 4; ni++) {
            int row0 = bm + wm * 32 + mi * 16 + lr;
            int col  = bn + wn * 32 + ni * 8 + (lc << 1);
            float b0 = bias[col], b1 = bias[col + 1];
#pragma unroll
            for (int half = 0; half < 2; half++) {
                int row = row0 + half * 8;
                float v0 = c[mi][ni][half * 2 + 0] + b0;
                float v1 = c[mi][ni][half * 2 + 1] + b1;
                if (mode == 1) {
                    float2 xo = *(const float2*)(xold + (size_t)row * DMC + col);
                    v0 = beta * v0 + omb * xo.x;
                    v1 = beta * v1 + omb * xo.y;
                }
                if (gelu_after) { v0 = gelu_f(v0); v1 = gelu_f(v1); }
                *(float2*)(C + (size_t)row * ldc + col) = make_float2(v0, v1);
            }
        }
    }
}

// ---------------------------------------------------------------------------
// Fused edge attention + aggregation + GELU.
// One warp per (dst, head): walks incoming edges via CSR, computes logits
// (q cached in registers), softmax, weighted vt gather; writes gelu(agg).
__global__ __launch_bounds__(256)
void agg_kernel(const int* __restrict__ rowptr, const int* __restrict__ col,
                const float* __restrict__ q, const float* __restrict__ kt,
                const float* __restrict__ vt, const float* __restrict__ prel,
                float* __restrict__ agg, int ndst) {
    int gid = blockIdx.x * blockDim.x + threadIdx.x;
    int w = gid >> 5;
    int lane = gid & 31;
    if (w >= ndst * NHC) return;
    int dN = w >> 2;
    int h = w & 3;
    int base = rowptr[dN];
    int deg = rowptr[dN + 1] - base;

    float accx = 0.0f, accy = 0.0f;
    if (deg > 0) {
        const size_t hoff = (size_t)h * NDC + lane * 2;
        float2 qv = *(const float2*)(q + (size_t)dN * LDPROJ + hoff);
        float pr = prel[h] * 0.125f;

        if (deg <= 32) {
            float lg0 = -INFINITY;
            float m = -INFINITY;
            for (int j = 0; j < deg; j++) {
                int s = col[base + j];
                float2 kv = *(const float2*)(kt + (size_t)s * LDPROJ + hoff);
                float p = qv.x * kv.x + qv.y * kv.y;
#pragma unroll
                for (int o = 16; o > 0; o >>= 1) p += __shfl_xor_sync(0xffffffffu, p, o);
                float lg = p * pr;
                if (j == lane) lg0 = lg;
                m = fmaxf(m, lg);
            }
            float e0 = (lane < deg) ? expf(lg0 - m) : 0.0f;
            float t = e0;
#pragma unroll
            for (int o = 16; o > 0; o >>= 1) t += __shfl_xor_sync(0xffffffffu, t, o);
            float inv = 1.0f / (t + 1e-16f);
            for (int j = 0; j < deg; j++) {
                float a = __shfl_sync(0xffffffffu, e0, j) * inv;
                int s = col[base + j];
                float2 v = *(const float2*)(vt + (size_t)s * LDPROJ + hoff);
                accx = fmaf(a, v.x, accx);
                accy = fmaf(a, v.y, accy);
            }
        } else {
            // recompute path (rare; any degree)
            float m = -INFINITY;
            for (int j = 0; j < deg; j++) {
                int s = col[base + j];
                float2 kv = *(const float2*)(kt + (size_t)s * LDPROJ + hoff);
                float p = qv.x * kv.x + qv.y * kv.y;
#pragma unroll
                for (int o = 16; o > 0; o >>= 1) p += __shfl_xor_sync(0xffffffffu, p, o);
                m = fmaxf(m, p * pr);
            }
            float ssum = 0.0f;
            for (int j = 0; j < deg; j++) {
                int s = col[base + j];
                float2 kv = *(const float2*)(kt + (size_t)s * LDPROJ + hoff);
                float p = qv.x * kv.x + qv.y * kv.y;
#pragma unroll
                for (int o = 16; o > 0; o >>= 1) p += __shfl_xor_sync(0xffffffffu, p, o);
                ssum += expf(p * pr - m);
            }
            float inv = 1.0f / (ssum + 1e-16f);
            for (int j = 0; j < deg; j++) {
                int s = col[base + j];
                float2 kv = *(const float2*)(kt + (size_t)s * LDPROJ + hoff);
                float p = qv.x * kv.x + qv.y * kv.y;
#pragma unroll
                for (int o = 16; o > 0; o >>= 1) p += __shfl_xor_sync(0xffffffffu, p, o);
                float a = expf(p * pr - m) * inv;
                float2 v = *(const float2*)(vt + (size_t)s * LDPROJ + hoff);
                accx = fmaf(a, v.x, accx);
                accy = fmaf(a, v.y, accy);
            }
        }
    }
    *(float2*)(agg + (size_t)dN * DMC + (size_t)h * NDC + lane * 2) =
        make_float2(gelu_f(accx), gelu_f(accy));
}

// ---------------------------------------------------------------------------
extern "C" void kernel_launch(void* const* d_in, const int* in_sizes, int n_in,
                              void* d_out, int out_size) {
    (void)in_sizes; (void)n_in; (void)out_size;

    float* base = nullptr;
    cudaGetSymbolAddress((void**)&base, g_buf);

    const int*   user_ids  = (const int*)d_in[0];
    const float* x_product = (const float*)d_in[1];
    const int*   edge_src  = (const int*)d_in[2];
    const int*   edge_dst  = (const int*)d_in[3];
    const float* emb       = (const float*)d_in[4];
    const float* Wk        = (const float*)d_in[5];
    const float* bk        = (const float*)d_in[6];
    const float* Wq        = (const float*)d_in[7];
    const float* bq        = (const float*)d_in[8];
    const float* Wv        = (const float*)d_in[9];
    const float* bv        = (const float*)d_in[10];
    const float* Wout      = (const float*)d_in[11];
    const float* bout      = (const float*)d_in[12];
    const float* skipp     = (const float*)d_in[13];
    const float* arel      = (const float*)d_in[14];
    const float* mrel      = (const float*)d_in[15];
    const float* prel      = (const float*)d_in[16];

    float* xuA   = base + OFF_XUA;
    float* xuB   = base + OFF_XUB;
    float* projU = base + OFF_PROJU;
    float* aggU  = base + OFF_AGGU;
    float* xpB   = base + OFF_XPB;
    float* projP = base + OFF_PROJP;
    float* aggP  = base + OFF_AGGP;
    float* Wbig  = base + OFF_WBIG;
    float* bbig  = base + OFF_BBIG;

    int* ibase   = (int*)(base + OFF_INT);
    int* rowptrP = ibase + I_ROWP;
    int* rowptrU = ibase + I_ROWU;
    int* degP    = ibase + I_DEGP;
    int* degU    = ibase + I_DEGU;
    int* curP    = ibase + I_CURP;
    int* curU    = ibase + I_CURU;
    int* colP    = ibase + I_COLP;
    int* colU    = ibase + I_COLU;

    float* out_xu = (float*)d_out;
    float* out_xp = (float*)d_out + SZ_U;

    // 1. Fused projection weights
    copyq_kernel<<<dim3(4, 256), 256>>>(Wq, bq, Wbig, bbig);
    fuse_w_kernel<<<dim3(8, 256), 256>>>(Wk, Wv, arel, mrel, Wbig);
    fuse_b_kernel<<<8, 256>>>(bk, bv, arel, mrel, bbig);

    // 2. Gather user embeddings
    {
        size_t n = (size_t)NUC * (DMC / 4);
        gather_kernel<<<(unsigned)((n + 255) / 256), 256>>>(user_ids, emb, xuA);
    }

    // 3. Build CSRs (both directions), reused across layers
    cudaMemsetAsync(degP, 0, (size_t)NPC * sizeof(int));
    cudaMemsetAsync(degU, 0, (size_t)NUC * sizeof(int));
    count_deg<<<(NEC + 255) / 256, 256>>>(edge_src, edge_dst, degP, degU);
    scan_kernel<<<1, 1024>>>(degP, rowptrP, curP, NPC);
    scan_kernel<<<1, 1024>>>(degU, rowptrU, curU, NUC);
    build_csr<<<(NEC + 255) / 256, 256>>>(edge_src, edge_dst, curP, curU, colP, colU);

    for (int l = 0; l < 2; l++) {
        const float* xu_in = l ? xuB : xuA;
        const float* xp_in = l ? xpB : x_product;
        float* xu_out = l ? out_xu : xuB;
        float* xp_out = l ? out_xp : xpB;
        int gelu_after = (l == 0) ? 1 : 0;

        // Projections: one [M,256]x[256,768] GEMM per node type
        {
            size_t cu = (size_t)(l * 2 + 0), cp = (size_t)(l * 2 + 1);
            gemm_tf32<<<dim3(6, NUC / 64), 256>>>(
                xu_in, DMC, Wbig + cu * DMC * LDPROJ, LDPROJ, bbig + cu * LDPROJ,
                projU, LDPROJ, 0, nullptr, nullptr, 0);
            gemm_tf32<<<dim3(6, NPC / 64), 256>>>(
                xp_in, DMC, Wbig + cp * DMC * LDPROJ, LDPROJ, bbig + cp * LDPROJ,
                projP, LDPROJ, 0, nullptr, nullptr, 0);
        }

        // rel 0: user -> product (dst = product); neighbors = user srcs
        {
            unsigned blocks = (unsigned)(((size_t)NPC * NHC * 32 + 255) / 256);
            agg_kernel<<<blocks, 256>>>(rowptrP, colP,
                                        projP /*q*/, projU + DMC /*kt*/, projU + 2 * DMC /*vt*/,
                                        prel + (size_t)(l * 2 + 0) * NHC, aggP, NPC);
        }
        // rel 1: product -> user (dst = user); neighbors = product ids
        {
            unsigned blocks = (unsigned)(((size_t)NUC * NHC * 32 + 255) / 256);
            agg_kernel<<<blocks, 256>>>(rowptrU, colU,
                                        projU /*q*/, projP + DMC /*kt*/, projP + 2 * DMC /*vt*/,
                                        prel + (size_t)(l * 2 + 1) * NHC, aggU, NUC);
        }

        // Output GEMMs with skip blend (+ inter-layer gelu fused for l==0)
        {
            gemm_tf32<<<dim3(2, NPC / 64), 256>>>(
                aggP, DMC, Wout + (size_t)(l * 2 + 1) * DMC * DMC, DMC,
                bout + (size_t)(l * 2 + 1) * DMC, xp_out, DMC,
                1, xp_in, skipp + (l * 2 + 1), gelu_after);
            gemm_tf32<<<dim3(2, NUC / 64), 256>>>(
                aggU, DMC, Wout + (size_t)(l * 2 + 0) * DMC * DMC, DMC,
                bout + (size_t)(l * 2 + 0) * DMC, xu_out, DMC,
                1, xu_in, skipp + (l * 2 + 0), gelu_after);
        }
    }
}